// round 9
// baseline (speedup 1.0000x reference)
#include <cuda_runtime.h>
#include <cstdint>

#define B 32
#define L 4096
#define D 768
#define DG (D / 4)              // 192 float4 channel groups
#define WINDOW 32
#define LN_EPS 1e-5f
#define S 8                     // splits (CTAs) per batch
#define NTHREADS DG             // 192 threads per CTA
#define NWARPS_LN (DG / 32)     // 6
#define CTR_STRIDE 32           // 128B between counters -> distinct LTS lines

// Partial pooled sums: [B][S][DG] float4, and per-batch arrival counters.
__device__ float4 vdp_part[B * S * DG];
__device__ int    vdp_ctr[B * CTR_STRIDE];   // zero-init at load; reset by finalizer

__global__ __launch_bounds__(NTHREADS, 8)
void vdp_lastblock8b(const float* __restrict__ ref_repr,
                     const float* __restrict__ alt_repr,
                     const int* __restrict__ variant_pos,
                     const float* __restrict__ gamma,
                     const float* __restrict__ beta,
                     float* __restrict__ out) {
    const int s = blockIdx.x;       // split 0..S-1
    const int b = blockIdx.y;       // batch
    const int c = threadIdx.x;      // channel group 0..191

    const int p  = __ldg(&variant_pos[b]);
    const int lo = max(0, p - WINDOW);
    const int hi = min(L - 1, p + WINDOW);
    const int n  = hi - lo + 1;     // 33..65
    const float inv_count = 1.0f / (float)n;

    const float4* __restrict__ rb =
        (const float4*)ref_repr + (size_t)b * L * DG + (size_t)lo * DG + c;
    const float4* __restrict__ ab =
        (const float4*)alt_repr + (size_t)b * L * DG + (size_t)lo * DG + c;

    // Rows s, s+S, ... (<= 9 rows => <= 18 independent LDG.128 per thread)
    float4 acc = make_float4(0.f, 0.f, 0.f, 0.f);
    #pragma unroll 3
    for (int i = s; i < n; i += S) {
        float4 a = ab[(size_t)i * DG];
        float4 r = rb[(size_t)i * DG];
        acc.x += a.x - r.x;
        acc.y += a.y - r.y;
        acc.z += a.z - r.z;
        acc.w += a.w - r.w;
    }

    // Publish this CTA's partial.
    vdp_part[((size_t)b * S + s) * DG + c] = acc;

    // Election: bar orders all CTA partial stores; the cumulative gpu-scope
    // acq_rel atomic releases them to (and acquires them from) peer CTAs.
    // __syncthreads_or broadcasts the election result in the same barrier.
    __syncthreads();
    int pred = 0;
    if (c == 0) {
        int prev;
        int* ctr = &vdp_ctr[b * CTR_STRIDE];
        asm volatile("atom.add.acq_rel.gpu.global.s32 %0, [%1], 1;"
                     : "=r"(prev) : "l"(ctr) : "memory");
        pred = (prev == S - 1);
        if (pred) *ctr = 0;            // reset for next graph replay (off critical path)
    }
    if (!__syncthreads_or(pred)) return;

    // Prefetch epilogue params: overlap their L2 latency with the fold.
    const float4 g  = ((const float4*)gamma)[c];
    const float4 be = ((const float4*)beta)[c];

    // Fold all 8 partials in fixed order (deterministic), all L2-hot,
    // 8 independent LDG.128 -> one latency depth.
    const float4* __restrict__ pp = vdp_part + (size_t)b * S * DG + c;
    float4 t0 = make_float4(0.f, 0.f, 0.f, 0.f);
    #pragma unroll
    for (int r = 0; r < S; ++r) {
        float4 v = pp[(size_t)r * DG];
        t0.x += v.x; t0.y += v.y; t0.z += v.z; t0.w += v.w;
    }
    float4 pooled;
    pooled.x = t0.x * inv_count;
    pooled.y = t0.y * inv_count;
    pooled.z = t0.z * inv_count;
    pooled.w = t0.w * inv_count;

    // LayerNorm reduce over D across 192 threads (6 warps), single barrier:
    // every warp redundantly folds the 6 warp sums -> no broadcast barrier.
    __shared__ float red_s[NWARPS_LN];
    __shared__ float red_q[NWARPS_LN];

    const int lane = c & 31;
    const int warp = c >> 5;
    float vs = pooled.x + pooled.y + pooled.z + pooled.w;
    float vq = pooled.x * pooled.x + pooled.y * pooled.y
             + pooled.z * pooled.z + pooled.w * pooled.w;
    #pragma unroll
    for (int off = 16; off > 0; off >>= 1) {
        vs += __shfl_down_sync(0xffffffffu, vs, off);
        vq += __shfl_down_sync(0xffffffffu, vq, off);
    }
    if (lane == 0) { red_s[warp] = vs; red_q[warp] = vq; }
    __syncthreads();

    float ts = (lane < NWARPS_LN) ? red_s[lane] : 0.0f;
    float tq = (lane < NWARPS_LN) ? red_q[lane] : 0.0f;
    #pragma unroll
    for (int off = 4; off > 0; off >>= 1) {       // butterfly over 8 lanes
        ts += __shfl_xor_sync(0xffffffffu, ts, off);
        tq += __shfl_xor_sync(0xffffffffu, tq, off);
    }
    ts = __shfl_sync(0xffffffffu, ts, 0);
    tq = __shfl_sync(0xffffffffu, tq, 0);

    const float mu   = ts * (1.0f / (float)D);
    const float var  = tq * (1.0f / (float)D) - mu * mu;
    const float rstd = rsqrtf(var + LN_EPS);

    float4 o;
    o.x = (pooled.x - mu) * rstd * g.x + be.x;
    o.y = (pooled.y - mu) * rstd * g.y + be.y;
    o.z = (pooled.z - mu) * rstd * g.z + be.z;
    o.w = (pooled.w - mu) * rstd * g.w + be.w;
    ((float4*)out)[(size_t)b * DG + c] = o;
}

extern "C" void kernel_launch(void* const* d_in, const int* in_sizes, int n_in,
                              void* d_out, int out_size) {
    const float* ref_repr    = (const float*)d_in[0];
    const float* alt_repr    = (const float*)d_in[1];
    const int*   variant_pos = (const int*)d_in[2];
    const float* gamma       = (const float*)d_in[3];
    const float* beta        = (const float*)d_in[4];
    float* out = (float*)d_out;

    dim3 grid(S, B);
    vdp_lastblock8b<<<grid, NTHREADS>>>(ref_repr, alt_repr, variant_pos, gamma, beta, out);
}

// round 10
// speedup vs baseline: 1.0295x; 1.0295x over previous
#include <cuda_runtime.h>
#include <cstdint>

#define B 32
#define L 4096
#define D 768
#define DG (D / 4)              // 192 float4 channel groups
#define WINDOW 32
#define LN_EPS 1e-5f
#define S 8                     // splits (CTAs) per batch
#define NTHREADS DG             // 192 threads per CTA
#define NWARPS_LN (DG / 32)     // 6
#define CTR_STRIDE 32           // 128B between counters -> distinct LTS lines

// Partial pooled sums: [B][S][DG] float4, and per-batch arrival counters.
__device__ float4 vdp_part[B * S * DG];
__device__ int    vdp_ctr[B * CTR_STRIDE];   // zero-init at load; reset by finalizer

__global__ __launch_bounds__(NTHREADS, 8)
void vdp_lastblock8(const float* __restrict__ ref_repr,
                    const float* __restrict__ alt_repr,
                    const int* __restrict__ variant_pos,
                    const float* __restrict__ gamma,
                    const float* __restrict__ beta,
                    float* __restrict__ out) {
    const int s = blockIdx.x;       // split 0..S-1
    const int b = blockIdx.y;       // batch
    const int c = threadIdx.x;      // channel group 0..191

    const int p  = variant_pos[b];
    const int lo = max(0, p - WINDOW);
    const int hi = min(L - 1, p + WINDOW);
    const int n  = hi - lo + 1;     // 33..65
    const float inv_count = 1.0f / (float)n;

    const float4* __restrict__ rb =
        (const float4*)ref_repr + (size_t)b * L * DG + (size_t)lo * DG + c;
    const float4* __restrict__ ab =
        (const float4*)alt_repr + (size_t)b * L * DG + (size_t)lo * DG + c;

    // Rows s, s+S, ... (<= 9 rows => <= 18 independent LDG.128 per thread)
    float4 acc = make_float4(0.f, 0.f, 0.f, 0.f);
    #pragma unroll 3
    for (int i = s; i < n; i += S) {
        float4 a = ab[(size_t)i * DG];
        float4 r = rb[(size_t)i * DG];
        acc.x += a.x - r.x;
        acc.y += a.y - r.y;
        acc.z += a.z - r.z;
        acc.w += a.w - r.w;
    }

    // Publish this CTA's partial.
    vdp_part[((size_t)b * S + s) * DG + c] = acc;

    // Election. __syncthreads() orders all CTA partial stores; the cumulative
    // gpu-scope acq_rel atomic releases them to (and acquires them from) peers.
    __shared__ int is_last;
    __syncthreads();
    if (c == 0) {
        int prev;
        int* ctr = &vdp_ctr[b * CTR_STRIDE];
        asm volatile("atom.add.acq_rel.gpu.global.s32 %0, [%1], 1;"
                     : "=r"(prev) : "l"(ctr) : "memory");
        is_last = (prev == S - 1);
        if (prev == S - 1) *ctr = 0;   // reset for next graph replay
    }
    __syncthreads();
    if (!is_last) return;

    // Fold the other 7 partials (fixed order => deterministic), L2-hot.
    const float4* __restrict__ pp = vdp_part + (size_t)b * S * DG + c;
    #pragma unroll
    for (int r = 0; r < S; ++r) {
        if (r == s) continue;        // own contribution already in acc
        float4 v = pp[(size_t)r * DG];
        acc.x += v.x; acc.y += v.y; acc.z += v.z; acc.w += v.w;
    }
    float4 pooled;
    pooled.x = acc.x * inv_count;
    pooled.y = acc.y * inv_count;
    pooled.z = acc.z * inv_count;
    pooled.w = acc.w * inv_count;

    // LayerNorm reduce over D across 192 threads (6 warps).
    __shared__ float red_s[NWARPS_LN];
    __shared__ float red_q[NWARPS_LN];
    __shared__ float mu_sh, rstd_sh;

    const int lane = c & 31;
    const int warp = c >> 5;
    float vs = pooled.x + pooled.y + pooled.z + pooled.w;
    float vq = pooled.x * pooled.x + pooled.y * pooled.y
             + pooled.z * pooled.z + pooled.w * pooled.w;
    #pragma unroll
    for (int off = 16; off > 0; off >>= 1) {
        vs += __shfl_down_sync(0xffffffffu, vs, off);
        vq += __shfl_down_sync(0xffffffffu, vq, off);
    }
    if (lane == 0) { red_s[warp] = vs; red_q[warp] = vq; }
    __syncthreads();
    if (warp == 0) {
        float ts = (lane < NWARPS_LN) ? red_s[lane] : 0.0f;
        float tq = (lane < NWARPS_LN) ? red_q[lane] : 0.0f;
        #pragma unroll
        for (int off = 4; off > 0; off >>= 1) {
            ts += __shfl_down_sync(0xffffffffu, ts, off);
            tq += __shfl_down_sync(0xffffffffu, tq, off);
        }
        if (lane == 0) {
            const float mu  = ts * (1.0f / (float)D);
            const float var = tq * (1.0f / (float)D) - mu * mu;
            mu_sh   = mu;
            rstd_sh = rsqrtf(var + LN_EPS);
        }
    }
    __syncthreads();

    const float mu   = mu_sh;
    const float rstd = rstd_sh;
    const float4 g  = ((const float4*)gamma)[c];
    const float4 be = ((const float4*)beta)[c];
    float4 o;
    o.x = (pooled.x - mu) * rstd * g.x + be.x;
    o.y = (pooled.y - mu) * rstd * g.y + be.y;
    o.z = (pooled.z - mu) * rstd * g.z + be.z;
    o.w = (pooled.w - mu) * rstd * g.w + be.w;
    ((float4*)out)[(size_t)b * DG + c] = o;
}

extern "C" void kernel_launch(void* const* d_in, const int* in_sizes, int n_in,
                              void* d_out, int out_size) {
    const float* ref_repr    = (const float*)d_in[0];
    const float* alt_repr    = (const float*)d_in[1];
    const int*   variant_pos = (const int*)d_in[2];
    const float* gamma       = (const float*)d_in[3];
    const float* beta        = (const float*)d_in[4];
    float* out = (float*)d_out;

    dim3 grid(S, B);
    vdp_lastblock8<<<grid, NTHREADS>>>(ref_repr, alt_repr, variant_pos, gamma, beta, out);
}